// round 13
// baseline (speedup 1.0000x reference)
#include <cuda_runtime.h>
#include <cuda_fp16.h>
#include <cstdint>

#define E_ 8
#define H_ 2048
#define I_ 4096
#define T_ 1024

// ---------------- scratch: 96 MB — proven static footprint ------------------
__device__ __half g_xh[(size_t)E_ * T_ * H_];        // fp16 activations
__device__ __half g_inter[(size_t)E_ * T_ * I_];     // fp16 intermediate

// ---------------- helpers ----------------
// Exact e2m1 decode: codes 0..7 -> {0,.5,1,1.5,2,3,4,6}, bit3 = sign.
__device__ __forceinline__ float fp4f(int c) {
    int h = c & 7;
    int bits = (h < 2) ? h * 0x3F000000 : (((126 + (h >> 1)) << 23) | ((h & 1) << 22));
    bits |= (c & 8) << 28;
    return __int_as_float(bits);
}

__device__ __forceinline__ uint32_t pack2(float a, float b) {
    __half2 t = __floats2half2_rn(a, b);
    return *reinterpret_cast<uint32_t*>(&t);
}

__device__ __forceinline__ void cpasync16(__half* dst, const __half* src) {
    uint32_t d = (uint32_t)__cvta_generic_to_shared(dst);
    asm volatile("cp.async.cg.shared.global [%0], [%1], 16;" :: "r"(d), "l"(src));
}
#define CP_COMMIT() asm volatile("cp.async.commit_group;")
#define CP_WAIT0()  asm volatile("cp.async.wait_group 0;")

#define LDSM4(d0,d1,d2,d3,ptr) \
    asm volatile("ldmatrix.sync.aligned.m8n8.x4.shared.b16 {%0,%1,%2,%3},[%4];" \
        : "=r"(d0),"=r"(d1),"=r"(d2),"=r"(d3) : "r"(ptr))

__device__ __forceinline__ void mma16816(float& d0, float& d1, float& d2, float& d3,
                                         uint32_t a0, uint32_t a1, uint32_t a2, uint32_t a3,
                                         uint32_t b0, uint32_t b1) {
    asm volatile(
        "mma.sync.aligned.m16n8k16.row.col.f32.f16.f16.f32 "
        "{%0,%1,%2,%3},{%4,%5,%6,%7},{%8,%9},{%0,%1,%2,%3};\n"
        : "+f"(d0), "+f"(d1), "+f"(d2), "+f"(d3)
        : "r"(a0), "r"(a1), "r"(a2), "r"(a3), "r"(b0), "r"(b1));
}

__device__ __forceinline__ float silu_f(float v) { return v / (1.f + __expf(-v)); }

// smem row stride in halves (80 B): conflict-free for ldmatrix / STS.128.
#define STR 40

// ---------------------------------------------------------------------------
// Kernel 0: fp32 -> fp16 activation convert
// ---------------------------------------------------------------------------
__global__ void convert_x_kernel(const float* __restrict__ x) {
    int i = (blockIdx.x * blockDim.x + threadIdx.x) * 4;
    float4 v = *reinterpret_cast<const float4*>(x + i);
    __half2* o = reinterpret_cast<__half2*>(g_xh + i);
    o[0] = __floats2half2_rn(v.x, v.y);
    o[1] = __floats2half2_rn(v.z, v.w);
}

// ---------------------------------------------------------------------------
// Kernel 1: gemm1 (x @ Wgu) + fused SiLU-gate, in-loop dequant, pipelined.
// BM=128 x BN=64 pairs, BK=32, double-buffered; 512 threads = 16 warps (4x4),
// warp tile 32x16 gate + 32x16 up. Per-thread state ~90 regs -> no spills,
// 4 warps/SMSP (2x R7's latency hiding). Smem static 40,960 B (proven).
// ---------------------------------------------------------------------------
__global__ void __launch_bounds__(512) gemm1_silu_kernel(
    const int*   __restrict__ gup,     // [E, H/2, 2I]
    const float* __restrict__ gus,     // [E, H/16, 2I]
    const float* __restrict__ pgs)
{
    __shared__ __half As[2][128 * STR];
    __shared__ __half Bg[2][64 * STR];
    __shared__ __half Bu[2][64 * STR];

    const int e   = blockIdx.z;
    const int bm0 = blockIdx.x * 128;   // m-tile fastest -> weight L2 reuse
    const int n0  = blockIdx.y * 64;
    const float gscale = __ldg(pgs);

    const int tid  = threadIdx.x;
    const int lane = tid & 31;
    const int wid  = tid >> 5;          // 0..15
    const int g    = lane >> 2;
    const int tg   = lane & 3;
    const int wm   = wid & 3;           // 0..3 (32 rows each)
    const int wn   = wid >> 2;          // 0..3 (16 cols each)

    float accg[2][2][4], accu[2][2][4];
#pragma unroll
    for (int a = 0; a < 2; a++)
#pragma unroll
        for (int b = 0; b < 2; b++)
#pragma unroll
            for (int c = 0; c < 4; c++) { accg[a][b][c] = 0.f; accu[a][b][c] = 0.f; }

    const __half* xg = g_xh + (size_t)(e * T_ + bm0) * H_;

    // ldmatrix lane addressing
    const int a_r = wm * 32 + (lane & 15);
    const int a_c = (lane >> 4) * 8;
    const int b_r = (lane & 7) + ((lane >> 4) << 3);
    const int b_c = ((lane >> 3) & 1) * 8;

    // B loader: col = tid&63, quad = (tid>>6)&3 (4 kp rows), gu = tid>>8
    const int bcol = tid & 63;
    const int bq   = (tid >> 6) & 3;
    const int bgu  = tid >> 8;
    const int bncol = n0 + bcol + (bgu ? I_ : 0);

    int   pv[4];
    float bscale;

    auto loadB = [&](int k0) {
        const int kp0 = (k0 >> 1) + bq * 4;
        const int* p = gup + ((size_t)e * (H_ / 2) + kp0) * (2 * I_) + bncol;
#pragma unroll
        for (int j = 0; j < 4; j++) pv[j] = __ldg(p + (size_t)j * (2 * I_));
        bscale = __ldg(gus + ((size_t)e * (H_ / 16) + (kp0 >> 3)) * (2 * I_) + bncol) * gscale;
    };
    auto stsB = [&](int s) {
        uint32_t w[4];
#pragma unroll
        for (int j = 0; j < 4; j++)
            w[j] = pack2(fp4f(pv[j] & 15) * bscale, fp4f((pv[j] >> 4) & 15) * bscale);
        __half* d = (bgu ? Bu[s] : Bg[s]) + bcol * STR + 2 * (bq * 4);
        *reinterpret_cast<uint4*>(d) = make_uint4(w[0], w[1], w[2], w[3]);
    };
    auto loadA = [&](int s, int k0) {
        const int row = tid >> 2, seg = (tid & 3) * 8;   // 512 threads = full tile
        cpasync16(As[s] + row * STR + seg, xg + (size_t)row * H_ + k0 + seg);
    };

    auto mmastep = [&](int s, int kk) {
        uint32_t a[2][4];
#pragma unroll
        for (int mi = 0; mi < 2; mi++) {
            uint32_t p = (uint32_t)__cvta_generic_to_shared(
                As[s] + (a_r + mi * 16) * STR + kk * 16 + a_c);
            LDSM4(a[mi][0], a[mi][1], a[mi][2], a[mi][3], p);
        }
        uint32_t bg[4], bu[4];
        {
            uint32_t pg = (uint32_t)__cvta_generic_to_shared(
                Bg[s] + (wn * 16 + b_r) * STR + kk * 16 + b_c);
            LDSM4(bg[0], bg[1], bg[2], bg[3], pg);
            uint32_t pu = (uint32_t)__cvta_generic_to_shared(
                Bu[s] + (wn * 16 + b_r) * STR + kk * 16 + b_c);
            LDSM4(bu[0], bu[1], bu[2], bu[3], pu);
        }
#pragma unroll
        for (int ni = 0; ni < 2; ni++) {
#pragma unroll
            for (int mi = 0; mi < 2; mi++) {
                mma16816(accg[mi][ni][0], accg[mi][ni][1], accg[mi][ni][2], accg[mi][ni][3],
                         a[mi][0], a[mi][1], a[mi][2], a[mi][3],
                         bg[2 * ni], bg[2 * ni + 1]);
                mma16816(accu[mi][ni][0], accu[mi][ni][1], accu[mi][ni][2], accu[mi][ni][3],
                         a[mi][0], a[mi][1], a[mi][2], a[mi][3],
                         bu[2 * ni], bu[2 * ni + 1]);
            }
        }
    };

    // prologue
    loadB(0);
    loadA(0, 0);
    CP_COMMIT();
    stsB(0);
    CP_WAIT0();
    __syncthreads();

    const int NIT = H_ / 32;
    int s = 0;
    for (int it = 0; it < NIT; it++) {
        const bool more = (it + 1 < NIT);
        if (more) { loadB((it + 1) * 32); loadA(s ^ 1, (it + 1) * 32); }
        CP_COMMIT();

        mmastep(s, 0);
        if (more) stsB(s ^ 1);     // dequant ALU overlaps tensor-pipe drain
        mmastep(s, 1);

        CP_WAIT0();
        __syncthreads();
        s ^= 1;
    }

    // ---- epilogue: inter = up * silu(gate) ----
#pragma unroll
    for (int mi = 0; mi < 2; mi++) {
        const int r0 = bm0 + wm * 32 + mi * 16 + g;
#pragma unroll
        for (int ni = 0; ni < 2; ni++) {
            const int c0 = n0 + wn * 16 + ni * 8 + 2 * tg;
            const float i0 = accu[mi][ni][0] * silu_f(accg[mi][ni][0]);
            const float i1 = accu[mi][ni][1] * silu_f(accg[mi][ni][1]);
            const float i2 = accu[mi][ni][2] * silu_f(accg[mi][ni][2]);
            const float i3 = accu[mi][ni][3] * silu_f(accg[mi][ni][3]);
            *reinterpret_cast<__half2*>(g_inter + (size_t)(e * T_ + r0) * I_ + c0)
                = __floats2half2_rn(i0, i1);
            *reinterpret_cast<__half2*>(g_inter + (size_t)(e * T_ + r0 + 8) * I_ + c0)
                = __floats2half2_rn(i2, i3);
        }
    }
}

// ---------------------------------------------------------------------------
// Kernel 2: gemm2 (inter @ Wd) -> fp32.  512 threads = 16 warps (4x4),
// warp tile 32x32. BM=128 x BN=128, BK=32, double-buffered.
// ---------------------------------------------------------------------------
__global__ void __launch_bounds__(512) gemm2_kernel(
    const int*   __restrict__ dpk,     // [E, I/2, H]
    const float* __restrict__ dsc,     // [E, I/16, H]
    const float* __restrict__ pgs,
    float*       __restrict__ out)     // [E*T, H]
{
    __shared__ __half As[2][128 * STR];
    __shared__ __half Bs[2][128 * STR];

    const int e   = blockIdx.z;
    const int bm0 = blockIdx.x * 128;
    const int n0  = blockIdx.y * 128;
    const float gscale = __ldg(pgs);

    const int tid  = threadIdx.x;
    const int lane = tid & 31;
    const int wid  = tid >> 5;          // 0..15
    const int g    = lane >> 2;
    const int tg   = lane & 3;
    const int wm   = wid & 3;           // 0..3 (32 rows)
    const int wn   = wid >> 2;          // 0..3 (32 cols)

    float acc[2][4][4];
#pragma unroll
    for (int a = 0; a < 2; a++)
#pragma unroll
        for (int b = 0; b < 4; b++)
#pragma unroll
            for (int c = 0; c < 4; c++) acc[a][b][c] = 0.f;

    const __half* ag = g_inter + (size_t)(e * T_ + bm0) * I_;

    const int a_r = wm * 32 + (lane & 15);
    const int a_c = (lane >> 4) * 8;
    const int b_r = (lane & 7) + ((lane >> 4) << 3);
    const int b_c = ((lane >> 3) & 1) * 8;

    // B loader: col = tid&127, quad = tid>>7 (0..3, 4 kp rows each)
    const int bcol = tid & 127;
    const int bq   = tid >> 7;

    int   pv[4];
    float bscale;

    auto loadB = [&](int k0) {
        const int kp0 = (k0 >> 1) + bq * 4;
        const int* p = dpk + ((size_t)e * (I_ / 2) + kp0) * H_ + n0 + bcol;
#pragma unroll
        for (int j = 0; j < 4; j++) pv[j] = __ldg(p + (size_t)j * H_);
        bscale = __ldg(dsc + ((size_t)e * (I_ / 16) + (kp0 >> 3)) * H_ + n0 + bcol) * gscale;
    };
    auto stsB = [&](int s) {
        uint32_t w[4];
#pragma unroll
        for (int j = 0; j < 4; j++)
            w[j] = pack2(fp4f(pv[j] & 15) * bscale, fp4f((pv[j] >> 4) & 15) * bscale);
        __half* d = Bs[s] + bcol * STR + 2 * (bq * 4);
        *reinterpret_cast<uint4*>(d) = make_uint4(w[0], w[1], w[2], w[3]);
    };
    auto loadA = [&](int s, int k0) {
        const int row = tid >> 2, seg = (tid & 3) * 8;
        cpasync16(As[s] + row * STR + seg, ag + (size_t)row * I_ + k0 + seg);
    };

    auto mmastep = [&](int s, int kk) {
        uint32_t a[2][4];
#pragma unroll
        for (int mi = 0; mi < 2; mi++) {
            uint32_t p = (uint32_t)__cvta_generic_to_shared(
                As[s] + (a_r + mi * 16) * STR + kk * 16 + a_c);
            LDSM4(a[mi][0], a[mi][1], a[mi][2], a[mi][3], p);
        }
        uint32_t bq2[2][4];
#pragma unroll
        for (int h = 0; h < 2; h++) {
            uint32_t p = (uint32_t)__cvta_generic_to_shared(
                Bs[s] + (wn * 32 + h * 16 + b_r) * STR + kk * 16 + b_c);
            LDSM4(bq2[h][0], bq2[h][1], bq2[h][2], bq2[h][3], p);
        }
#pragma unroll
        for (int ni = 0; ni < 4; ni++) {
            const uint32_t b0 = bq2[ni >> 1][2 * (ni & 1)];
            const uint32_t b1 = bq2[ni >> 1][2 * (ni & 1) + 1];
#pragma unroll
            for (int mi = 0; mi < 2; mi++) {
                mma16816(acc[mi][ni][0], acc[mi][ni][1], acc[mi][ni][2], acc[mi][ni][3],
                         a[mi][0], a[mi][1], a[mi][2], a[mi][3], b0, b1);
            }
        }
    };

    loadB(0);
    loadA(0, 0);
    CP_COMMIT();
    stsB(0);
    CP_WAIT0();
    __syncthreads();

    const int NIT = I_ / 32;
    int s = 0;
    for (int it = 0; it < NIT; it++) {
        const bool more = (it + 1 < NIT);
        if (more) { loadB((it + 1) * 32); loadA(s ^ 1, (it + 1) * 32); }
        CP_COMMIT();

        mmastep(s, 0);
        if (more) stsB(s ^ 1);
        mmastep(s, 1);

        CP_WAIT0();
        __syncthreads();
        s ^= 1;
    }

    // ---- epilogue ----
#pragma unroll
    for (int mi = 0; mi < 2; mi++) {
        const int r0 = bm0 + wm * 32 + mi * 16 + g;
#pragma unroll
        for (int ni = 0; ni < 4; ni++) {
            const int c0 = n0 + wn * 32 + ni * 8 + 2 * tg;
            *reinterpret_cast<float2*>(out + (size_t)(e * T_ + r0) * H_ + c0)
                = make_float2(acc[mi][ni][0], acc[mi][ni][1]);
            *reinterpret_cast<float2*>(out + (size_t)(e * T_ + r0 + 8) * H_ + c0)
                = make_float2(acc[mi][ni][2], acc[mi][ni][3]);
        }
    }
}

// ---------------------------------------------------------------------------
// Launch
// ---------------------------------------------------------------------------
extern "C" void kernel_launch(void* const* d_in, const int* in_sizes, int n_in,
                              void* d_out, int out_size) {
    const float* x   = (const float*)d_in[0];
    const int*   gup = (const int*)  d_in[1];
    const float* gus = (const float*)d_in[2];
    const float* gug = (const float*)d_in[3];
    const int*   dpk = (const int*)  d_in[4];
    const float* dsc = (const float*)d_in[5];
    const float* dgs = (const float*)d_in[6];
    float* out = (float*)d_out;

    convert_x_kernel<<<(E_ * T_ * H_) / 1024, 256>>>(x);

    gemm1_silu_kernel<<<dim3(T_ / 128, I_ / 64, E_), 512>>>(gup, gus, gug);
    gemm2_kernel<<<dim3(T_ / 128, H_ / 128, E_), 512>>>(dpk, dsc, dgs, out);
}

// round 14
// speedup vs baseline: 1.5539x; 1.5539x over previous
#include <cuda_runtime.h>
#include <cuda_fp16.h>
#include <cstdint>

#define E_ 8
#define H_ 2048
#define I_ 4096
#define T_ 1024

// ---------------- scratch: 96 MB — proven static footprint ------------------
__device__ __half g_xh[(size_t)E_ * T_ * H_];        // fp16 activations
__device__ __half g_inter[(size_t)E_ * T_ * I_];     // fp16 intermediate

// ---------------- helpers ----------------
// Exact e2m1 decode: codes 0..7 -> {0,.5,1,1.5,2,3,4,6}, bit3 = sign.
__device__ __forceinline__ float fp4f(int c) {
    int h = c & 7;
    int bits = (h < 2) ? h * 0x3F000000 : (((126 + (h >> 1)) << 23) | ((h & 1) << 22));
    bits |= (c & 8) << 28;
    return __int_as_float(bits);
}

__device__ __forceinline__ uint32_t pack2(float a, float b) {
    __half2 t = __floats2half2_rn(a, b);
    return *reinterpret_cast<uint32_t*>(&t);
}

__device__ __forceinline__ void cpasync16(__half* dst, const __half* src) {
    uint32_t d = (uint32_t)__cvta_generic_to_shared(dst);
    asm volatile("cp.async.cg.shared.global [%0], [%1], 16;" :: "r"(d), "l"(src));
}
#define CP_COMMIT() asm volatile("cp.async.commit_group;")
#define CP_WAIT0()  asm volatile("cp.async.wait_group 0;")

#define LDSM4(d0,d1,d2,d3,ptr) \
    asm volatile("ldmatrix.sync.aligned.m8n8.x4.shared.b16 {%0,%1,%2,%3},[%4];" \
        : "=r"(d0),"=r"(d1),"=r"(d2),"=r"(d3) : "r"(ptr))

__device__ __forceinline__ void mma16816(float& d0, float& d1, float& d2, float& d3,
                                         uint32_t a0, uint32_t a1, uint32_t a2, uint32_t a3,
                                         uint32_t b0, uint32_t b1) {
    asm volatile(
        "mma.sync.aligned.m16n8k16.row.col.f32.f16.f16.f32 "
        "{%0,%1,%2,%3},{%4,%5,%6,%7},{%8,%9},{%0,%1,%2,%3};\n"
        : "+f"(d0), "+f"(d1), "+f"(d2), "+f"(d3)
        : "r"(a0), "r"(a1), "r"(a2), "r"(a3), "r"(b0), "r"(b1));
}

__device__ __forceinline__ float silu_f(float v) { return v / (1.f + __expf(-v)); }

// smem row stride in halves (80 B): conflict-free for ldmatrix / STS.128.
#define STR 40

// ---------------------------------------------------------------------------
// Kernel 0: fp32 -> fp16 activation convert
// ---------------------------------------------------------------------------
__global__ void convert_x_kernel(const float* __restrict__ x) {
    int i = (blockIdx.x * blockDim.x + threadIdx.x) * 4;
    float4 v = *reinterpret_cast<const float4*>(x + i);
    __half2* o = reinterpret_cast<__half2*>(g_xh + i);
    o[0] = __floats2half2_rn(v.x, v.y);
    o[1] = __floats2half2_rn(v.z, v.w);
}

// ---------------------------------------------------------------------------
// Kernel 1: gemm1 (x @ Wgu) + fused SiLU-gate. R7 structure verbatim
// (BM=128 x BN=64 pairs, BK=32, double-buffered, ldmatrix, 256 thr);
// dequant via 256-entry smem float2 LUT (bit-identical values to fp4f).
// ---------------------------------------------------------------------------
__global__ void __launch_bounds__(256) gemm1_silu_kernel(
    const int*   __restrict__ gup,     // [E, H/2, 2I]
    const float* __restrict__ gus,     // [E, H/16, 2I]
    const float* __restrict__ pgs)     // scalar gscale
{
    __shared__ __half As[2][128 * STR];
    __shared__ __half Bg[2][64 * STR];
    __shared__ __half Bu[2][64 * STR];
    __shared__ float2 s_lut[256];

    const int e   = blockIdx.z;
    const int bm0 = blockIdx.x * 128;   // m-tile fastest -> weight L2 reuse
    const int n0  = blockIdx.y * 64;
    const float gscale = __ldg(pgs);

    const int tid  = threadIdx.x;
    const int lane = tid & 31;
    const int wid  = tid >> 5;
    const int g    = lane >> 2;
    const int tg   = lane & 3;
    const int wm   = wid & 1;
    const int wn   = wid >> 1;

    // byte -> (lo-nibble value, hi-nibble value), exact fp4f outputs
    if (tid < 256) s_lut[tid] = make_float2(fp4f(tid & 15), fp4f(tid >> 4));
    __syncthreads();

    float accg[4][2][4], accu[4][2][4];
#pragma unroll
    for (int a = 0; a < 4; a++)
#pragma unroll
        for (int b = 0; b < 2; b++)
#pragma unroll
            for (int c = 0; c < 4; c++) { accg[a][b][c] = 0.f; accu[a][b][c] = 0.f; }

    const __half* xg = g_xh + (size_t)(e * T_ + bm0) * H_;

    // ldmatrix lane addressing (verified R7)
    const int a_r = wm * 64 + (lane & 15);
    const int a_c = (lane >> 4) * 8;
    const int b_r = (lane & 7) + ((lane >> 4) << 3);
    const int b_c = ((lane >> 3) & 1) * 8;

    // B loader: col = tid&63, oct = (tid>>6)&1 (one 16-k scale block), gu = tid>>7
    const int bcol = tid & 63;
    const int boct = (tid >> 6) & 1;
    const int bgu  = tid >> 7;
    const int bncol = n0 + bcol + (bgu ? I_ : 0);

    int   pv[8];
    float bscale;

    auto loadB = [&](int k0) {
        const int kp0 = (k0 >> 1) + boct * 8;
        const int* p = gup + ((size_t)e * (H_ / 2) + kp0) * (2 * I_) + bncol;
#pragma unroll
        for (int j = 0; j < 8; j++) pv[j] = __ldg(p + (size_t)j * (2 * I_));
        bscale = __ldg(gus + ((size_t)e * (H_ / 16) + (kp0 >> 3)) * (2 * I_) + bncol) * gscale;
    };
    auto stsB = [&](int s) {
        uint32_t w[8];
#pragma unroll
        for (int j = 0; j < 8; j++) {
            const float2 lu = s_lut[pv[j] & 255];
            w[j] = pack2(lu.x * bscale, lu.y * bscale);
        }
        __half* d = (bgu ? Bu[s] : Bg[s]) + bcol * STR + 2 * (boct * 8);
        reinterpret_cast<uint4*>(d)[0] = make_uint4(w[0], w[1], w[2], w[3]);
        reinterpret_cast<uint4*>(d)[1] = make_uint4(w[4], w[5], w[6], w[7]);
    };
    auto loadA = [&](int s, int k0) {
#pragma unroll
        for (int i = 0; i < 2; i++) {
            const int u = tid + 256 * i;            // 0..511
            const int row = u >> 2, seg = (u & 3) * 8;
            cpasync16(As[s] + row * STR + seg, xg + (size_t)row * H_ + k0 + seg);
        }
    };

    auto mmastep = [&](int s, int kk) {
        uint32_t a[4][4];
#pragma unroll
        for (int mi = 0; mi < 4; mi++) {
            uint32_t p = (uint32_t)__cvta_generic_to_shared(
                As[s] + (a_r + mi * 16) * STR + kk * 16 + a_c);
            LDSM4(a[mi][0], a[mi][1], a[mi][2], a[mi][3], p);
        }
        uint32_t bg[4], bu[4];
        {
            uint32_t pg = (uint32_t)__cvta_generic_to_shared(
                Bg[s] + (wn * 16 + b_r) * STR + kk * 16 + b_c);
            LDSM4(bg[0], bg[1], bg[2], bg[3], pg);
            uint32_t pu = (uint32_t)__cvta_generic_to_shared(
                Bu[s] + (wn * 16 + b_r) * STR + kk * 16 + b_c);
            LDSM4(bu[0], bu[1], bu[2], bu[3], pu);
        }
#pragma unroll
        for (int ni = 0; ni < 2; ni++) {
#pragma unroll
            for (int mi = 0; mi < 4; mi++) {
                mma16816(accg[mi][ni][0], accg[mi][ni][1], accg[mi][ni][2], accg[mi][ni][3],
                         a[mi][0], a[mi][1], a[mi][2], a[mi][3],
                         bg[2 * ni], bg[2 * ni + 1]);
                mma16816(accu[mi][ni][0], accu[mi][ni][1], accu[mi][ni][2], accu[mi][ni][3],
                         a[mi][0], a[mi][1], a[mi][2], a[mi][3],
                         bu[2 * ni], bu[2 * ni + 1]);
            }
        }
    };

    // prologue
    loadB(0);
    loadA(0, 0);
    CP_COMMIT();
    stsB(0);
    CP_WAIT0();
    __syncthreads();

    const int NIT = H_ / 32;
    int s = 0;
    for (int it = 0; it < NIT; it++) {
        const bool more = (it + 1 < NIT);
        if (more) { loadB((it + 1) * 32); loadA(s ^ 1, (it + 1) * 32); }
        CP_COMMIT();

        mmastep(s, 0);
        if (more) stsB(s ^ 1);     // dequant (now ~3x cheaper) overlaps drain
        mmastep(s, 1);

        CP_WAIT0();
        __syncthreads();
        s ^= 1;
    }

    // ---- epilogue (verbatim R7): inter = up * silu(gate) ----
#pragma unroll
    for (int mi = 0; mi < 4; mi++) {
        const int r0 = bm0 + wm * 64 + mi * 16 + g;
#pragma unroll
        for (int ni = 0; ni < 2; ni++) {
            const int c0 = n0 + wn * 16 + ni * 8 + 2 * tg;
            const float i0 = accu[mi][ni][0] * silu_f(accg[mi][ni][0]);
            const float i1 = accu[mi][ni][1] * silu_f(accg[mi][ni][1]);
            const float i2 = accu[mi][ni][2] * silu_f(accg[mi][ni][2]);
            const float i3 = accu[mi][ni][3] * silu_f(accg[mi][ni][3]);
            *reinterpret_cast<__half2*>(g_inter + (size_t)(e * T_ + r0) * I_ + c0)
                = __floats2half2_rn(i0, i1);
            *reinterpret_cast<__half2*>(g_inter + (size_t)(e * T_ + r0 + 8) * I_ + c0)
                = __floats2half2_rn(i2, i3);
        }
    }
}

// ---------------------------------------------------------------------------
// Kernel 2: gemm2 (inter @ Wd) -> fp32. R7 structure verbatim + LUT dequant.
// ---------------------------------------------------------------------------
__global__ void __launch_bounds__(256) gemm2_kernel(
    const int*   __restrict__ dpk,     // [E, I/2, H]
    const float* __restrict__ dsc,     // [E, I/16, H]
    const float* __restrict__ pgs,
    float*       __restrict__ out)     // [E*T, H]
{
    __shared__ __half As[2][128 * STR];
    __shared__ __half Bs[2][128 * STR];
    __shared__ float2 s_lut[256];

    const int e   = blockIdx.z;
    const int bm0 = blockIdx.x * 128;
    const int n0  = blockIdx.y * 128;
    const float gscale = __ldg(pgs);

    const int tid  = threadIdx.x;
    const int lane = tid & 31;
    const int wid  = tid >> 5;
    const int g    = lane >> 2;
    const int tg   = lane & 3;
    const int wm   = wid & 1;
    const int wn   = wid >> 1;

    if (tid < 256) s_lut[tid] = make_float2(fp4f(tid & 15), fp4f(tid >> 4));
    __syncthreads();

    float acc[4][4][4];
#pragma unroll
    for (int a = 0; a < 4; a++)
#pragma unroll
        for (int b = 0; b < 4; b++)
#pragma unroll
            for (int c = 0; c < 4; c++) acc[a][b][c] = 0.f;

    const __half* ag = g_inter + (size_t)(e * T_ + bm0) * I_;

    const int a_r = wm * 64 + (lane & 15);
    const int a_c = (lane >> 4) * 8;
    const int b_r = (lane & 7) + ((lane >> 4) << 3);
    const int b_c = ((lane >> 3) & 1) * 8;

    const int bcol = tid & 127;
    const int boct = tid >> 7;

    int   pv[8];
    float bscale;

    auto loadB = [&](int k0) {
        const int kp0 = (k0 >> 1) + boct * 8;
        const int* p = dpk + ((size_t)e * (I_ / 2) + kp0) * H_ + n0 + bcol;
#pragma unroll
        for (int j = 0; j < 8; j++) pv[j] = __ldg(p + (size_t)j * H_);
        bscale = __ldg(dsc + ((size_t)e * (I_ / 16) + (kp0 >> 3)) * H_ + n0 + bcol) * gscale;
    };
    auto stsB = [&](int s) {
        uint32_t w[8];
#pragma unroll
        for (int j = 0; j < 8; j++) {
            const float2 lu = s_lut[pv[j] & 255];
            w[j] = pack2(lu.x * bscale, lu.y * bscale);
        }
        __half* d = Bs[s] + bcol * STR + 2 * (boct * 8);
        reinterpret_cast<uint4*>(d)[0] = make_uint4(w[0], w[1], w[2], w[3]);
        reinterpret_cast<uint4*>(d)[1] = make_uint4(w[4], w[5], w[6], w[7]);
    };
    auto loadA = [&](int s, int k0) {
#pragma unroll
        for (int i = 0; i < 2; i++) {
            const int u = tid + 256 * i;
            const int row = u >> 2, seg = (u & 3) * 8;
            cpasync16(As[s] + row * STR + seg, ag + (size_t)row * I_ + k0 + seg);
        }
    };

    auto mmastep = [&](int s, int kk) {
        uint32_t a[4][4];
#pragma unroll
        for (int mi = 0; mi < 4; mi++) {
            uint32_t p = (uint32_t)__cvta_generic_to_shared(
                As[s] + (a_r + mi * 16) * STR + kk * 16 + a_c);
            LDSM4(a[mi][0], a[mi][1], a[mi][2], a[mi][3], p);
        }
        uint32_t bq[2][4];
#pragma unroll
        for (int h = 0; h < 2; h++) {
            uint32_t p = (uint32_t)__cvta_generic_to_shared(
                Bs[s] + (wn * 32 + h * 16 + b_r) * STR + kk * 16 + b_c);
            LDSM4(bq[h][0], bq[h][1], bq[h][2], bq[h][3], p);
        }
#pragma unroll
        for (int ni = 0; ni < 4; ni++) {
            const uint32_t b0 = bq[ni >> 1][2 * (ni & 1)];
            const uint32_t b1 = bq[ni >> 1][2 * (ni & 1) + 1];
#pragma unroll
            for (int mi = 0; mi < 4; mi++) {
                mma16816(acc[mi][ni][0], acc[mi][ni][1], acc[mi][ni][2], acc[mi][ni][3],
                         a[mi][0], a[mi][1], a[mi][2], a[mi][3], b0, b1);
            }
        }
    };

    loadB(0);
    loadA(0, 0);
    CP_COMMIT();
    stsB(0);
    CP_WAIT0();
    __syncthreads();

    const int NIT = I_ / 32;
    int s = 0;
    for (int it = 0; it < NIT; it++) {
        const bool more = (it + 1 < NIT);
        if (more) { loadB((it + 1) * 32); loadA(s ^ 1, (it + 1) * 32); }
        CP_COMMIT();

        mmastep(s, 0);
        if (more) stsB(s ^ 1);
        mmastep(s, 1);

        CP_WAIT0();
        __syncthreads();
        s ^= 1;
    }

    // ---- epilogue (verbatim R7) ----
#pragma unroll
    for (int mi = 0; mi < 4; mi++) {
        const int r0 = bm0 + wm * 64 + mi * 16 + g;
#pragma unroll
        for (int ni = 0; ni < 4; ni++) {
            const int c0 = n0 + wn * 32 + ni * 8 + 2 * tg;
            *reinterpret_cast<float2*>(out + (size_t)(e * T_ + r0) * H_ + c0)
                = make_float2(acc[mi][ni][0], acc[mi][ni][1]);
            *reinterpret_cast<float2*>(out + (size_t)(e * T_ + r0 + 8) * H_ + c0)
                = make_float2(acc[mi][ni][2], acc[mi][ni][3]);
        }
    }
}

// ---------------------------------------------------------------------------
// Launch
// ---------------------------------------------------------------------------
extern "C" void kernel_launch(void* const* d_in, const int* in_sizes, int n_in,
                              void* d_out, int out_size) {
    const float* x   = (const float*)d_in[0];
    const int*   gup = (const int*)  d_in[1];
    const float* gus = (const float*)d_in[2];
    const float* gug = (const float*)d_in[3];
    const int*   dpk = (const int*)  d_in[4];
    const float* dsc = (const float*)d_in[5];
    const float* dgs = (const float*)d_in[6];
    float* out = (float*)d_out;

    convert_x_kernel<<<(E_ * T_ * H_) / 1024, 256>>>(x);

    gemm1_silu_kernel<<<dim3(T_ / 128, I_ / 64, E_), 256>>>(gup, gus, gug);
    gemm2_kernel<<<dim3(T_ / 128, H_ / 128, E_), 256>>>(dpk, dsc, dgs, out);
}

// round 15
// speedup vs baseline: 1.5696x; 1.0101x over previous
#include <cuda_runtime.h>
#include <cuda_fp16.h>
#include <cstdint>

#define E_ 8
#define H_ 2048
#define I_ 4096
#define T_ 1024

// ---------------- scratch: 96 MB — proven static footprint ------------------
__device__ __half g_xh[(size_t)E_ * T_ * H_];        // fp16 activations
__device__ __half g_inter[(size_t)E_ * T_ * I_];     // fp16 intermediate

// ---------------- helpers ----------------
// Exact e2m1 decode: codes 0..7 -> {0,.5,1,1.5,2,3,4,6}, bit3 = sign.
__device__ __forceinline__ float fp4f(int c) {
    int h = c & 7;
    int bits = (h < 2) ? h * 0x3F000000 : (((126 + (h >> 1)) << 23) | ((h & 1) << 22));
    bits |= (c & 8) << 28;
    return __int_as_float(bits);
}

__device__ __forceinline__ uint32_t pack2(float a, float b) {
    __half2 t = __floats2half2_rn(a, b);
    return *reinterpret_cast<uint32_t*>(&t);
}

__device__ __forceinline__ void cpa16(uint32_t dsm, const void* src) {
    asm volatile("cp.async.cg.shared.global [%0], [%1], 16;" :: "r"(dsm), "l"(src));
}
__device__ __forceinline__ void cpa4(uint32_t dsm, const void* src) {
    asm volatile("cp.async.ca.shared.global [%0], [%1], 4;" :: "r"(dsm), "l"(src));
}
#define CP_COMMIT() asm volatile("cp.async.commit_group;")
#define CP_WAIT1()  asm volatile("cp.async.wait_group 1;")

#define LDSM4(d0,d1,d2,d3,ptr) \
    asm volatile("ldmatrix.sync.aligned.m8n8.x4.shared.b16 {%0,%1,%2,%3},[%4];" \
        : "=r"(d0),"=r"(d1),"=r"(d2),"=r"(d3) : "r"(ptr))

__device__ __forceinline__ void mma16816(float& d0, float& d1, float& d2, float& d3,
                                         uint32_t a0, uint32_t a1, uint32_t a2, uint32_t a3,
                                         uint32_t b0, uint32_t b1) {
    asm volatile(
        "mma.sync.aligned.m16n8k16.row.col.f32.f16.f16.f32 "
        "{%0,%1,%2,%3},{%4,%5,%6,%7},{%8,%9},{%0,%1,%2,%3};\n"
        : "+f"(d0), "+f"(d1), "+f"(d2), "+f"(d3)
        : "r"(a0), "r"(a1), "r"(a2), "r"(a3), "r"(b0), "r"(b1));
}

__device__ __forceinline__ uint32_t lds_u32(uint32_t a) {
    uint32_t v;
    asm volatile("ld.shared.b32 %0, [%1];" : "=r"(v) : "r"(a));
    return v;
}

__device__ __forceinline__ float silu_f(float v) { return v / (1.f + __expf(-v)); }

// smem row stride in halves (80 B): conflict-free for ldmatrix / STS.128.
#define STR 40

// dynamic smem layout (byte offsets), identical for both gemms:
//   [0, 30720)      A stages: 3 x (128*STR*2 = 10240)
//   [30720, 51200)  B fp16 buffers: 2 x 10240
//   [51200, 79712)  B packed staging: 3 x 9504   (9 planes x 1056 B;
//                   plane j: value j of each thread at tid*4; plane 8: scale)
#define A_ST_B   10240
#define BBUF_OFF 30720
#define BBUF_B   10240
#define BP_OFF   51200
#define BP_ST_B  9504
#define BP_PLANE 1056
#define SMEM_BYTES 79712

// ---------------------------------------------------------------------------
// Kernel 0: fp32 -> fp16 activation convert
// ---------------------------------------------------------------------------
__global__ void convert_x_kernel(const float* __restrict__ x) {
    int i = (blockIdx.x * blockDim.x + threadIdx.x) * 4;
    float4 v = *reinterpret_cast<const float4*>(x + i);
    __half2* o = reinterpret_cast<__half2*>(g_xh + i);
    o[0] = __floats2half2_rn(v.x, v.y);
    o[1] = __floats2half2_rn(v.z, v.w);
}

// ---------------------------------------------------------------------------
// Kernel 1: gemm1 (x @ Wgu) + fused SiLU-gate. R7 loop verbatim except the
// B path: packed ints + scale staged via per-thread cp.async planes (3-deep),
// dequant reads back own bytes after wait_group (no extra barrier).
// ---------------------------------------------------------------------------
__global__ void __launch_bounds__(256) gemm1_silu_kernel(
    const int*   __restrict__ gup,     // [E, H/2, 2I]
    const float* __restrict__ gus,     // [E, H/16, 2I]
    const float* __restrict__ pgs)     // scalar gscale
{
    extern __shared__ __align__(16) char smraw[];
    const uint32_t smb = (uint32_t)__cvta_generic_to_shared(smraw);
    __half* const smh = reinterpret_cast<__half*>(smraw);

    const int e   = blockIdx.z;
    const int bm0 = blockIdx.x * 128;   // m-tile fastest -> weight L2 reuse
    const int n0  = blockIdx.y * 64;
    const float gscale = __ldg(pgs);

    const int tid  = threadIdx.x;
    const int lane = tid & 31;
    const int wid  = tid >> 5;
    const int g    = lane >> 2;
    const int tg   = lane & 3;
    const int wm   = wid & 1;
    const int wn   = wid >> 1;

    float accg[4][2][4], accu[4][2][4];
#pragma unroll
    for (int a = 0; a < 4; a++)
#pragma unroll
        for (int b = 0; b < 2; b++)
#pragma unroll
            for (int c = 0; c < 4; c++) { accg[a][b][c] = 0.f; accu[a][b][c] = 0.f; }

    const __half* xg = g_xh + (size_t)(e * T_ + bm0) * H_;

    // ldmatrix lane addressing (verified R7)
    const int a_r = wm * 64 + (lane & 15);
    const int a_c = (lane >> 4) * 8;
    const int b_r = (lane & 7) + ((lane >> 4) << 3);
    const int b_c = ((lane >> 3) & 1) * 8;

    // B thread mapping (verified R7): col = tid&63, oct = (tid>>6)&1, gu = tid>>7
    const int bcol = tid & 63;
    const int boct = (tid >> 6) & 1;
    const int bgu  = tid >> 7;
    const int bncol = n0 + bcol + (bgu ? I_ : 0);

    // ---- staging helpers ----
    auto stageB = [&](int st, int k0) {
        const int kp0 = (k0 >> 1) + boct * 8;
        const int* p = gup + ((size_t)e * (H_ / 2) + kp0) * (2 * I_) + bncol;
        const uint32_t bp = smb + BP_OFF + st * BP_ST_B + tid * 4;
#pragma unroll
        for (int j = 0; j < 8; j++)
            cpa4(bp + j * BP_PLANE, p + (size_t)j * (2 * I_));
        cpa4(bp + 8 * BP_PLANE,
             gus + ((size_t)e * (H_ / 16) + (kp0 >> 3)) * (2 * I_) + bncol);
    };
    auto stageA = [&](int st, int k0) {
        const uint32_t ab = smb + st * A_ST_B;
#pragma unroll
        for (int i = 0; i < 2; i++) {
            const int u = tid + 256 * i;
            const int row = u >> 2, seg = (u & 3) * 8;
            cpa16(ab + (row * STR + seg) * 2, xg + (size_t)row * H_ + k0 + seg);
        }
    };
    // dequant stage st -> fp16 buffer buf (reads only this thread's planes)
    auto dequantB = [&](int st, int buf) {
        const uint32_t bp = smb + BP_OFF + st * BP_ST_B + tid * 4;
        const float bscale = __uint_as_float(lds_u32(bp + 8 * BP_PLANE)) * gscale;
        uint32_t w[8];
#pragma unroll
        for (int j = 0; j < 8; j++) {
            const int v = (int)lds_u32(bp + j * BP_PLANE);
            w[j] = pack2(fp4f(v & 15) * bscale, fp4f((v >> 4) & 15) * bscale);
        }
        // Bg at BBUF_OFF + buf*BBUF_B, Bu at +64*STR*2 within the buffer
        __half* d = smh + (BBUF_OFF + buf * BBUF_B) / 2 + (bgu ? 64 * STR : 0)
                  + bcol * STR + 2 * (boct * 8);
        reinterpret_cast<uint4*>(d)[0] = make_uint4(w[0], w[1], w[2], w[3]);
        reinterpret_cast<uint4*>(d)[1] = make_uint4(w[4], w[5], w[6], w[7]);
    };

    auto mmastep = [&](int s, int buf, int kk) {
        const uint32_t As = smb + s * A_ST_B;
        const uint32_t Bb = smb + BBUF_OFF + buf * BBUF_B;
        uint32_t a[4][4];
#pragma unroll
        for (int mi = 0; mi < 4; mi++) {
            uint32_t p = As + ((a_r + mi * 16) * STR + kk * 16 + a_c) * 2;
            LDSM4(a[mi][0], a[mi][1], a[mi][2], a[mi][3], p);
        }
        uint32_t bg[4], bu[4];
        {
            uint32_t pg = Bb + ((wn * 16 + b_r) * STR + kk * 16 + b_c) * 2;
            LDSM4(bg[0], bg[1], bg[2], bg[3], pg);
            uint32_t pu = Bb + ((64 + wn * 16 + b_r) * STR + kk * 16 + b_c) * 2;
            LDSM4(bu[0], bu[1], bu[2], bu[3], pu);
        }
#pragma unroll
        for (int ni = 0; ni < 2; ni++) {
#pragma unroll
            for (int mi = 0; mi < 4; mi++) {
                mma16816(accg[mi][ni][0], accg[mi][ni][1], accg[mi][ni][2], accg[mi][ni][3],
                         a[mi][0], a[mi][1], a[mi][2], a[mi][3],
                         bg[2 * ni], bg[2 * ni + 1]);
                mma16816(accu[mi][ni][0], accu[mi][ni][1], accu[mi][ni][2], accu[mi][ni][3],
                         a[mi][0], a[mi][1], a[mi][2], a[mi][3],
                         bu[2 * ni], bu[2 * ni + 1]);
            }
        }
    };

    const int NIT = H_ / 32;   // 64

    // ---- prologue ----
    stageA(0, 0);  stageB(0, 0);  CP_COMMIT();     // G0
    stageA(1, 32); stageB(1, 32); CP_COMMIT();     // G1
    CP_WAIT1();                                     // G0 done
    __syncthreads();                                // A0 visible CTA-wide
    dequantB(0, 0);                                 // own bytes: no barrier needed
    __syncthreads();                                // Bbuf0 visible

    for (int it = 0; it < NIT; it++) {
        const bool more  = (it + 1 < NIT);
        const bool more2 = (it + 2 < NIT);
        if (more2) { stageA((it + 2) % 3, (it + 2) * 32); stageB((it + 2) % 3, (it + 2) * 32); }
        CP_COMMIT();

        const int s = it % 3, buf = it & 1;
        mmastep(s, buf, 0);
        CP_WAIT1();                                 // group(it+1) complete
        if (more) dequantB((it + 1) % 3, buf ^ 1);  // overlaps MMA drain
        mmastep(s, buf, 1);
        __syncthreads();
    }

    // ---- epilogue (verbatim R7): inter = up * silu(gate) ----
#pragma unroll
    for (int mi = 0; mi < 4; mi++) {
        const int r0 = bm0 + wm * 64 + mi * 16 + g;
#pragma unroll
        for (int ni = 0; ni < 2; ni++) {
            const int c0 = n0 + wn * 16 + ni * 8 + 2 * tg;
            const float i0 = accu[mi][ni][0] * silu_f(accg[mi][ni][0]);
            const float i1 = accu[mi][ni][1] * silu_f(accg[mi][ni][1]);
            const float i2 = accu[mi][ni][2] * silu_f(accg[mi][ni][2]);
            const float i3 = accu[mi][ni][3] * silu_f(accg[mi][ni][3]);
            *reinterpret_cast<__half2*>(g_inter + (size_t)(e * T_ + r0) * I_ + c0)
                = __floats2half2_rn(i0, i1);
            *reinterpret_cast<__half2*>(g_inter + (size_t)(e * T_ + r0 + 8) * I_ + c0)
                = __floats2half2_rn(i2, i3);
        }
    }
}

// ---------------------------------------------------------------------------
// Kernel 2: gemm2 (inter @ Wd) -> fp32. Same staging scheme.
// ---------------------------------------------------------------------------
__global__ void __launch_bounds__(256) gemm2_kernel(
    const int*   __restrict__ dpk,     // [E, I/2, H]
    const float* __restrict__ dsc,     // [E, I/16, H]
    const float* __restrict__ pgs,
    float*       __restrict__ out)     // [E*T, H]
{
    extern __shared__ __align__(16) char smraw[];
    const uint32_t smb = (uint32_t)__cvta_generic_to_shared(smraw);
    __half* const smh = reinterpret_cast<__half*>(smraw);

    const int e   = blockIdx.z;
    const int bm0 = blockIdx.x * 128;
    const int n0  = blockIdx.y * 128;
    const float gscale = __ldg(pgs);

    const int tid  = threadIdx.x;
    const int lane = tid & 31;
    const int wid  = tid >> 5;
    const int g    = lane >> 2;
    const int tg   = lane & 3;
    const int wm   = wid & 1;
    const int wn   = wid >> 1;

    float acc[4][4][4];
#pragma unroll
    for (int a = 0; a < 4; a++)
#pragma unroll
        for (int b = 0; b < 4; b++)
#pragma unroll
            for (int c = 0; c < 4; c++) acc[a][b][c] = 0.f;

    const __half* ag = g_inter + (size_t)(e * T_ + bm0) * I_;

    const int a_r = wm * 64 + (lane & 15);
    const int a_c = (lane >> 4) * 8;
    const int b_r = (lane & 7) + ((lane >> 4) << 3);
    const int b_c = ((lane >> 3) & 1) * 8;

    const int bcol = tid & 127;
    const int boct = tid >> 7;

    auto stageB = [&](int st, int k0) {
        const int kp0 = (k0 >> 1) + boct * 8;
        const int* p = dpk + ((size_t)e * (I_ / 2) + kp0) * H_ + n0 + bcol;
        const uint32_t bp = smb + BP_OFF + st * BP_ST_B + tid * 4;
#pragma unroll
        for (int j = 0; j < 8; j++)
            cpa4(bp + j * BP_PLANE, p + (size_t)j * H_);
        cpa4(bp + 8 * BP_PLANE,
             dsc + ((size_t)e * (I_ / 16) + (kp0 >> 3)) * H_ + n0 + bcol);
    };
    auto stageA = [&](int st, int k0) {
        const uint32_t ab = smb + st * A_ST_B;
#pragma unroll
        for (int i = 0; i < 2; i++) {
            const int u = tid + 256 * i;
            const int row = u >> 2, seg = (u & 3) * 8;
            cpa16(ab + (row * STR + seg) * 2, ag + (size_t)row * I_ + k0 + seg);
        }
    };
    auto dequantB = [&](int st, int buf) {
        const uint32_t bp = smb + BP_OFF + st * BP_ST_B + tid * 4;
        const float bscale = __uint_as_float(lds_u32(bp + 8 * BP_PLANE)) * gscale;
        uint32_t w[8];
#pragma unroll
        for (int j = 0; j < 8; j++) {
            const int v = (int)lds_u32(bp + j * BP_PLANE);
            w[j] = pack2(fp4f(v & 15) * bscale, fp4f((v >> 4) & 15) * bscale);
        }
        __half* d = smh + (BBUF_OFF + buf * BBUF_B) / 2 + bcol * STR + 2 * (boct * 8);
        reinterpret_cast<uint4*>(d)[0] = make_uint4(w[0], w[1], w[2], w[3]);
        reinterpret_cast<uint4*>(d)[1] = make_uint4(w[4], w[5], w[6], w[7]);
    };

    auto mmastep = [&](int s, int buf, int kk) {
        const uint32_t As = smb + s * A_ST_B;
        const uint32_t Bb = smb + BBUF_OFF + buf * BBUF_B;
        uint32_t a[4][4];
#pragma unroll
        for (int mi = 0; mi < 4; mi++) {
            uint32_t p = As + ((a_r + mi * 16) * STR + kk * 16 + a_c) * 2;
            LDSM4(a[mi][0], a[mi][1], a[mi][2], a[mi][3], p);
        }
        uint32_t bq[2][4];
#pragma unroll
        for (int h = 0; h < 2; h++) {
            uint32_t p = Bb + ((wn * 32 + h * 16 + b_r) * STR + kk * 16 + b_c) * 2;
            LDSM4(bq[h][0], bq[h][1], bq[h][2], bq[h][3], p);
        }
#pragma unroll
        for (int ni = 0; ni < 4; ni++) {
            const uint32_t b0 = bq[ni >> 1][2 * (ni & 1)];
            const uint32_t b1 = bq[ni >> 1][2 * (ni & 1) + 1];
#pragma unroll
            for (int mi = 0; mi < 4; mi++) {
                mma16816(acc[mi][ni][0], acc[mi][ni][1], acc[mi][ni][2], acc[mi][ni][3],
                         a[mi][0], a[mi][1], a[mi][2], a[mi][3], b0, b1);
            }
        }
    };

    const int NIT = I_ / 32;   // 128

    stageA(0, 0);  stageB(0, 0);  CP_COMMIT();
    stageA(1, 32); stageB(1, 32); CP_COMMIT();
    CP_WAIT1();
    __syncthreads();
    dequantB(0, 0);
    __syncthreads();

    for (int it = 0; it < NIT; it++) {
        const bool more  = (it + 1 < NIT);
        const bool more2 = (it + 2 < NIT);
        if (more2) { stageA((it + 2) % 3, (it + 2) * 32); stageB((it + 2) % 3, (it + 2) * 32); }
        CP_COMMIT();

        const int s = it % 3, buf = it & 1;
        mmastep(s, buf, 0);
        CP_WAIT1();
        if (more) dequantB((it + 1) % 3, buf ^ 1);
        mmastep(s, buf, 1);
        __syncthreads();
    }

    // ---- epilogue (verbatim R7) ----
#pragma unroll
    for (int mi = 0; mi < 4; mi++) {
        const int r0 = bm0 + wm * 64 + mi * 16 + g;
#pragma unroll
        for (int ni = 0; ni < 4; ni++) {
            const int c0 = n0 + wn * 32 + ni * 8 + 2 * tg;
            *reinterpret_cast<float2*>(out + (size_t)(e * T_ + r0) * H_ + c0)
                = make_float2(acc[mi][ni][0], acc[mi][ni][1]);
            *reinterpret_cast<float2*>(out + (size_t)(e * T_ + r0 + 8) * H_ + c0)
                = make_float2(acc[mi][ni][2], acc[mi][ni][3]);
        }
    }
}

// ---------------------------------------------------------------------------
// Launch
// ---------------------------------------------------------------------------
extern "C" void kernel_launch(void* const* d_in, const int* in_sizes, int n_in,
                              void* d_out, int out_size) {
    const float* x   = (const float*)d_in[0];
    const int*   gup = (const int*)  d_in[1];
    const float* gus = (const float*)d_in[2];
    const float* gug = (const float*)d_in[3];
    const int*   dpk = (const int*)  d_in[4];
    const float* dsc = (const float*)d_in[5];
    const float* dgs = (const float*)d_in[6];
    float* out = (float*)d_out;

    static int init_done = 0;
    if (!init_done) {
        cudaFuncSetAttribute(gemm1_silu_kernel,
                             cudaFuncAttributeMaxDynamicSharedMemorySize, SMEM_BYTES);
        cudaFuncSetAttribute(gemm2_kernel,
                             cudaFuncAttributeMaxDynamicSharedMemorySize, SMEM_BYTES);
        init_done = 1;
    }

    convert_x_kernel<<<(E_ * T_ * H_) / 1024, 256>>>(x);

    gemm1_silu_kernel<<<dim3(T_ / 128, I_ / 64, E_), 256, SMEM_BYTES>>>(gup, gus, gug);
    gemm2_kernel<<<dim3(T_ / 128, H_ / 128, E_), 256, SMEM_BYTES>>>(dpk, dsc, dgs, out);
}

// round 16
// speedup vs baseline: 1.7329x; 1.1040x over previous
#include <cuda_runtime.h>
#include <cuda_fp16.h>
#include <cstdint>

#define E_ 8
#define H_ 2048
#define I_ 4096
#define T_ 1024

// ---------------- scratch: 96 MB — proven static footprint ------------------
__device__ __half g_xh[(size_t)E_ * T_ * H_];        // fp16 activations
__device__ __half g_inter[(size_t)E_ * T_ * I_];     // fp16 intermediate

// ---------------- helpers ----------------
// Exact e2m1 decode: codes 0..7 -> {0,.5,1,1.5,2,3,4,6}, bit3 = sign.
__device__ __forceinline__ float fp4f(int c) {
    int h = c & 7;
    int bits = (h < 2) ? h * 0x3F000000 : (((126 + (h >> 1)) << 23) | ((h & 1) << 22));
    bits |= (c & 8) << 28;
    return __int_as_float(bits);
}

__device__ __forceinline__ uint32_t pack2(float a, float b) {
    __half2 t = __floats2half2_rn(a, b);
    return *reinterpret_cast<uint32_t*>(&t);
}

__device__ __forceinline__ void cpasync16(__half* dst, const __half* src) {
    uint32_t d = (uint32_t)__cvta_generic_to_shared(dst);
    asm volatile("cp.async.cg.shared.global [%0], [%1], 16;" :: "r"(d), "l"(src));
}
#define CP_COMMIT() asm volatile("cp.async.commit_group;")
#define CP_WAIT0()  asm volatile("cp.async.wait_group 0;")

#define LDSM4(d0,d1,d2,d3,ptr) \
    asm volatile("ldmatrix.sync.aligned.m8n8.x4.shared.b16 {%0,%1,%2,%3},[%4];" \
        : "=r"(d0),"=r"(d1),"=r"(d2),"=r"(d3) : "r"(ptr))

__device__ __forceinline__ void mma16816(float& d0, float& d1, float& d2, float& d3,
                                         uint32_t a0, uint32_t a1, uint32_t a2, uint32_t a3,
                                         uint32_t b0, uint32_t b1) {
    asm volatile(
        "mma.sync.aligned.m16n8k16.row.col.f32.f16.f16.f32 "
        "{%0,%1,%2,%3},{%4,%5,%6,%7},{%8,%9},{%0,%1,%2,%3};\n"
        : "+f"(d0), "+f"(d1), "+f"(d2), "+f"(d3)
        : "r"(a0), "r"(a1), "r"(a2), "r"(a3), "r"(b0), "r"(b1));
}

__device__ __forceinline__ float silu_f(float v) { return v / (1.f + __expf(-v)); }

// smem row stride in halves (80 B): conflict-free for ldmatrix / STS.128.
#define STR 40

// ---------------------------------------------------------------------------
// Kernel 0: fp32 -> fp16 activation convert
// ---------------------------------------------------------------------------
__global__ void convert_x_kernel(const float* __restrict__ x) {
    int i = (blockIdx.x * blockDim.x + threadIdx.x) * 4;
    float4 v = *reinterpret_cast<const float4*>(x + i);
    __half2* o = reinterpret_cast<__half2*>(g_xh + i);
    o[0] = __floats2half2_rn(v.x, v.y);
    o[1] = __floats2half2_rn(v.z, v.w);
}

// ---------------------------------------------------------------------------
// Kernel 1: gemm1 (x @ Wgu) + fused SiLU-gate. Per-warp stream identical to
// R7 (warp tile 64x16 gate + 64x16 up, BK=32, double-buffered, ldmatrix,
// in-loop dequant pv[8]); CTA halved: 128 threads, BN=32 pairs, warps 2x2.
// 2 CTAs/SM -> two independent pipelines per SM (scheduler slack at barriers).
// Smem: 2*(128*40 + 2*32*40)*2 = 30,720 B static.
// ---------------------------------------------------------------------------
__global__ void __launch_bounds__(128) gemm1_silu_kernel(
    const int*   __restrict__ gup,     // [E, H/2, 2I]
    const float* __restrict__ gus,     // [E, H/16, 2I]
    const float* __restrict__ pgs)     // scalar gscale
{
    __shared__ __half As[2][128 * STR];
    __shared__ __half Bg[2][32 * STR];
    __shared__ __half Bu[2][32 * STR];

    const int e   = blockIdx.z;
    const int bm0 = blockIdx.x * 128;   // m-tile fastest -> weight L2 reuse
    const int n0  = blockIdx.y * 32;    // gate col tile (up = I_ + n0)
    const float gscale = __ldg(pgs);

    const int tid  = threadIdx.x;
    const int lane = tid & 31;
    const int wid  = tid >> 5;          // 0..3
    const int g    = lane >> 2;
    const int tg   = lane & 3;
    const int wm   = wid & 1;           // 0..1 (64 rows each)
    const int wn   = wid >> 1;          // 0..1 (16 cols each)

    float accg[4][2][4], accu[4][2][4];
#pragma unroll
    for (int a = 0; a < 4; a++)
#pragma unroll
        for (int b = 0; b < 2; b++)
#pragma unroll
            for (int c = 0; c < 4; c++) { accg[a][b][c] = 0.f; accu[a][b][c] = 0.f; }

    const __half* xg = g_xh + (size_t)(e * T_ + bm0) * H_;

    // ldmatrix lane addressing (verified R7)
    const int a_r = wm * 64 + (lane & 15);
    const int a_c = (lane >> 4) * 8;
    const int b_r = (lane & 7) + ((lane >> 4) << 3);
    const int b_c = ((lane >> 3) & 1) * 8;

    // B loader: col = tid&31, oct = (tid>>5)&1 (one 16-k scale block), gu = tid>>6
    const int bcol = tid & 31;
    const int boct = (tid >> 5) & 1;
    const int bgu  = tid >> 6;
    const int bncol = n0 + bcol + (bgu ? I_ : 0);

    int   pv[8];
    float bscale;

    auto loadB = [&](int k0) {
        const int kp0 = (k0 >> 1) + boct * 8;
        const int* p = gup + ((size_t)e * (H_ / 2) + kp0) * (2 * I_) + bncol;
#pragma unroll
        for (int j = 0; j < 8; j++) pv[j] = __ldg(p + (size_t)j * (2 * I_));
        bscale = __ldg(gus + ((size_t)e * (H_ / 16) + (kp0 >> 3)) * (2 * I_) + bncol) * gscale;
    };
    auto stsB = [&](int s) {
        uint32_t w[8];
#pragma unroll
        for (int j = 0; j < 8; j++)
            w[j] = pack2(fp4f(pv[j] & 15) * bscale, fp4f((pv[j] >> 4) & 15) * bscale);
        __half* d = (bgu ? Bu[s] : Bg[s]) + bcol * STR + 2 * (boct * 8);
        reinterpret_cast<uint4*>(d)[0] = make_uint4(w[0], w[1], w[2], w[3]);
        reinterpret_cast<uint4*>(d)[1] = make_uint4(w[4], w[5], w[6], w[7]);
    };
    auto loadA = [&](int s, int k0) {
#pragma unroll
        for (int i = 0; i < 4; i++) {
            const int u = tid + 128 * i;            // 0..511
            const int row = u >> 2, seg = (u & 3) * 8;
            cpasync16(As[s] + row * STR + seg, xg + (size_t)row * H_ + k0 + seg);
        }
    };

    auto mmastep = [&](int s, int kk) {
        uint32_t a[4][4];
#pragma unroll
        for (int mi = 0; mi < 4; mi++) {
            uint32_t p = (uint32_t)__cvta_generic_to_shared(
                As[s] + (a_r + mi * 16) * STR + kk * 16 + a_c);
            LDSM4(a[mi][0], a[mi][1], a[mi][2], a[mi][3], p);
        }
        uint32_t bg[4], bu[4];
        {
            uint32_t pg = (uint32_t)__cvta_generic_to_shared(
                Bg[s] + (wn * 16 + b_r) * STR + kk * 16 + b_c);
            LDSM4(bg[0], bg[1], bg[2], bg[3], pg);
            uint32_t pu = (uint32_t)__cvta_generic_to_shared(
                Bu[s] + (wn * 16 + b_r) * STR + kk * 16 + b_c);
            LDSM4(bu[0], bu[1], bu[2], bu[3], pu);
        }
#pragma unroll
        for (int ni = 0; ni < 2; ni++) {
#pragma unroll
            for (int mi = 0; mi < 4; mi++) {
                mma16816(accg[mi][ni][0], accg[mi][ni][1], accg[mi][ni][2], accg[mi][ni][3],
                         a[mi][0], a[mi][1], a[mi][2], a[mi][3],
                         bg[2 * ni], bg[2 * ni + 1]);
                mma16816(accu[mi][ni][0], accu[mi][ni][1], accu[mi][ni][2], accu[mi][ni][3],
                         a[mi][0], a[mi][1], a[mi][2], a[mi][3],
                         bu[2 * ni], bu[2 * ni + 1]);
            }
        }
    };

    // prologue
    loadB(0);
    loadA(0, 0);
    CP_COMMIT();
    stsB(0);
    CP_WAIT0();
    __syncthreads();

    const int NIT = H_ / 32;
    int s = 0;
    for (int it = 0; it < NIT; it++) {
        const bool more = (it + 1 < NIT);
        if (more) { loadB((it + 1) * 32); loadA(s ^ 1, (it + 1) * 32); }
        CP_COMMIT();

        mmastep(s, 0);
        if (more) stsB(s ^ 1);     // dequant ALU overlaps tensor-pipe drain
        mmastep(s, 1);

        CP_WAIT0();
        __syncthreads();
        s ^= 1;
    }

    // ---- epilogue: inter = up * silu(gate) ----
#pragma unroll
    for (int mi = 0; mi < 4; mi++) {
        const int r0 = bm0 + wm * 64 + mi * 16 + g;
#pragma unroll
        for (int ni = 0; ni < 2; ni++) {
            const int c0 = n0 + wn * 16 + ni * 8 + 2 * tg;
            const float i0 = accu[mi][ni][0] * silu_f(accg[mi][ni][0]);
            const float i1 = accu[mi][ni][1] * silu_f(accg[mi][ni][1]);
            const float i2 = accu[mi][ni][2] * silu_f(accg[mi][ni][2]);
            const float i3 = accu[mi][ni][3] * silu_f(accg[mi][ni][3]);
            *reinterpret_cast<__half2*>(g_inter + (size_t)(e * T_ + r0) * I_ + c0)
                = __floats2half2_rn(i0, i1);
            *reinterpret_cast<__half2*>(g_inter + (size_t)(e * T_ + r0 + 8) * I_ + c0)
                = __floats2half2_rn(i2, i3);
        }
    }
}

// ---------------------------------------------------------------------------
// Kernel 2: gemm2 (inter @ Wd) -> fp32. Per-warp stream identical to R7
// (warp tile 64x32); CTA halved: 128 threads, BN=64, warps 2x2. 2 CTAs/SM.
// Smem: 2*(128*40 + 64*40)*2 = 30,720 B static.
// ---------------------------------------------------------------------------
__global__ void __launch_bounds__(128) gemm2_kernel(
    const int*   __restrict__ dpk,     // [E, I/2, H]
    const float* __restrict__ dsc,     // [E, I/16, H]
    const float* __restrict__ pgs,
    float*       __restrict__ out)     // [E*T, H]
{
    __shared__ __half As[2][128 * STR];
    __shared__ __half Bs[2][64 * STR];

    const int e   = blockIdx.z;
    const int bm0 = blockIdx.x * 128;
    const int n0  = blockIdx.y * 64;
    const float gscale = __ldg(pgs);

    const int tid  = threadIdx.x;
    const int lane = tid & 31;
    const int wid  = tid >> 5;          // 0..3
    const int g    = lane >> 2;
    const int tg   = lane & 3;
    const int wm   = wid & 1;           // 0..1
    const int wn   = wid >> 1;          // 0..1 (32 cols each)

    float acc[4][4][4];
#pragma unroll
    for (int a = 0; a < 4; a++)
#pragma unroll
        for (int b = 0; b < 4; b++)
#pragma unroll
            for (int c = 0; c < 4; c++) acc[a][b][c] = 0.f;

    const __half* ag = g_inter + (size_t)(e * T_ + bm0) * I_;

    const int a_r = wm * 64 + (lane & 15);
    const int a_c = (lane >> 4) * 8;
    const int b_r = (lane & 7) + ((lane >> 4) << 3);
    const int b_c = ((lane >> 3) & 1) * 8;

    // B loader: col = tid&63, oct = tid>>6 (0..1); pv[8] each (R7 mapping)
    const int bcol = tid & 63;
    const int boct = tid >> 6;

    int   pv[8];
    float bscale;

    auto loadB = [&](int k0) {
        const int kp0 = (k0 >> 1) + boct * 8;
        const int* p = dpk + ((size_t)e * (I_ / 2) + kp0) * H_ + n0 + bcol;
#pragma unroll
        for (int j = 0; j < 8; j++) pv[j] = __ldg(p + (size_t)j * H_);
        bscale = __ldg(dsc + ((size_t)e * (I_ / 16) + (kp0 >> 3)) * H_ + n0 + bcol) * gscale;
    };
    auto stsB = [&](int s) {
        uint32_t w[8];
#pragma unroll
        for (int j = 0; j < 8; j++)
            w[j] = pack2(fp4f(pv[j] & 15) * bscale, fp4f((pv[j] >> 4) & 15) * bscale);
        __half* d = Bs[s] + bcol * STR + 2 * (boct * 8);
        reinterpret_cast<uint4*>(d)[0] = make_uint4(w[0], w[1], w[2], w[3]);
        reinterpret_cast<uint4*>(d)[1] = make_uint4(w[4], w[5], w[6], w[7]);
    };
    auto loadA = [&](int s, int k0) {
#pragma unroll
        for (int i = 0; i < 4; i++) {
            const int u = tid + 128 * i;
            const int row = u >> 2, seg = (u & 3) * 8;
            cpasync16(As[s] + row * STR + seg, ag + (size_t)row * I_ + k0 + seg);
        }
    };

    auto mmastep = [&](int s, int kk) {
        uint32_t a[4][4];
#pragma unroll
        for (int mi = 0; mi < 4; mi++) {
            uint32_t p = (uint32_t)__cvta_generic_to_shared(
                As[s] + (a_r + mi * 16) * STR + kk * 16 + a_c);
            LDSM4(a[mi][0], a[mi][1], a[mi][2], a[mi][3], p);
        }
        uint32_t bq[2][4];
#pragma unroll
        for (int h = 0; h < 2; h++) {
            uint32_t p = (uint32_t)__cvta_generic_to_shared(
                Bs[s] + (wn * 32 + h * 16 + b_r) * STR + kk * 16 + b_c);
            LDSM4(bq[h][0], bq[h][1], bq[h][2], bq[h][3], p);
        }
#pragma unroll
        for (int ni = 0; ni < 4; ni++) {
            const uint32_t b0 = bq[ni >> 1][2 * (ni & 1)];
            const uint32_t b1 = bq[ni >> 1][2 * (ni & 1) + 1];
#pragma unroll
            for (int mi = 0; mi < 4; mi++) {
                mma16816(acc[mi][ni][0], acc[mi][ni][1], acc[mi][ni][2], acc[mi][ni][3],
                         a[mi][0], a[mi][1], a[mi][2], a[mi][3], b0, b1);
            }
        }
    };

    loadB(0);
    loadA(0, 0);
    CP_COMMIT();
    stsB(0);
    CP_WAIT0();
    __syncthreads();

    const int NIT = I_ / 32;
    int s = 0;
    for (int it = 0; it < NIT; it++) {
        const bool more = (it + 1 < NIT);
        if (more) { loadB((it + 1) * 32); loadA(s ^ 1, (it + 1) * 32); }
        CP_COMMIT();

        mmastep(s, 0);
        if (more) stsB(s ^ 1);
        mmastep(s, 1);

        CP_WAIT0();
        __syncthreads();
        s ^= 1;
    }

    // ---- epilogue (verbatim R7) ----
#pragma unroll
    for (int mi = 0; mi < 4; mi++) {
        const int r0 = bm0 + wm * 64 + mi * 16 + g;
#pragma unroll
        for (int ni = 0; ni < 4; ni++) {
            const int c0 = n0 + wn * 32 + ni * 8 + 2 * tg;
            *reinterpret_cast<float2*>(out + (size_t)(e * T_ + r0) * H_ + c0)
                = make_float2(acc[mi][ni][0], acc[mi][ni][1]);
            *reinterpret_cast<float2*>(out + (size_t)(e * T_ + r0 + 8) * H_ + c0)
                = make_float2(acc[mi][ni][2], acc[mi][ni][3]);
        }
    }
}

// ---------------------------------------------------------------------------
// Launch
// ---------------------------------------------------------------------------
extern "C" void kernel_launch(void* const* d_in, const int* in_sizes, int n_in,
                              void* d_out, int out_size) {
    const float* x   = (const float*)d_in[0];
    const int*   gup = (const int*)  d_in[1];
    const float* gus = (const float*)d_in[2];
    const float* gug = (const float*)d_in[3];
    const int*   dpk = (const int*)  d_in[4];
    const float* dsc = (const float*)d_in[5];
    const float* dgs = (const float*)d_in[6];
    float* out = (float*)d_out;

    convert_x_kernel<<<(E_ * T_ * H_) / 1024, 256>>>(x);

    // m-tile fastest -> weight slab L2 reuse across co-resident m-blocks
    gemm1_silu_kernel<<<dim3(T_ / 128, I_ / 32, E_), 128>>>(gup, gus, gug);
    gemm2_kernel<<<dim3(T_ / 128, H_ / 64, E_), 128>>>(dpk, dsc, dgs, out);
}

// round 17
// speedup vs baseline: 1.7946x; 1.0356x over previous
#include <cuda_runtime.h>
#include <cuda_fp16.h>
#include <cstdint>

#define E_ 8
#define H_ 2048
#define I_ 4096
#define T_ 1024

// ---------------- scratch: 96 MB — proven static footprint ------------------
__device__ __half g_xh[(size_t)E_ * T_ * H_];        // fp16 activations
__device__ __half g_inter[(size_t)E_ * T_ * I_];     // fp16 intermediate

// ---------------- helpers ----------------
// Exact e2m1 decode: codes 0..7 -> {0,.5,1,1.5,2,3,4,6}, bit3 = sign.
__device__ __forceinline__ float fp4f(int c) {
    int h = c & 7;
    int bits = (h < 2) ? h * 0x3F000000 : (((126 + (h >> 1)) << 23) | ((h & 1) << 22));
    bits |= (c & 8) << 28;
    return __int_as_float(bits);
}

__device__ __forceinline__ uint32_t pack2(float a, float b) {
    __half2 t = __floats2half2_rn(a, b);
    return *reinterpret_cast<uint32_t*>(&t);
}

__device__ __forceinline__ void cpasync16(__half* dst, const __half* src) {
    uint32_t d = (uint32_t)__cvta_generic_to_shared(dst);
    asm volatile("cp.async.cg.shared.global [%0], [%1], 16;" :: "r"(d), "l"(src));
}
#define CP_COMMIT() asm volatile("cp.async.commit_group;")
#define CP_WAIT0()  asm volatile("cp.async.wait_group 0;")

#define LDSM4(d0,d1,d2,d3,ptr) \
    asm volatile("ldmatrix.sync.aligned.m8n8.x4.shared.b16 {%0,%1,%2,%3},[%4];" \
        : "=r"(d0),"=r"(d1),"=r"(d2),"=r"(d3) : "r"(ptr))

__device__ __forceinline__ void mma16816(float& d0, float& d1, float& d2, float& d3,
                                         uint32_t a0, uint32_t a1, uint32_t a2, uint32_t a3,
                                         uint32_t b0, uint32_t b1) {
    asm volatile(
        "mma.sync.aligned.m16n8k16.row.col.f32.f16.f16.f32 "
        "{%0,%1,%2,%3},{%4,%5,%6,%7},{%8,%9},{%0,%1,%2,%3};\n"
        : "+f"(d0), "+f"(d1), "+f"(d2), "+f"(d3)
        : "r"(a0), "r"(a1), "r"(a2), "r"(a3), "r"(b0), "r"(b1));
}

__device__ __forceinline__ float silu_f(float v) { return v / (1.f + __expf(-v)); }

// smem row stride in halves (80 B): conflict-free for ldmatrix / STS.128.
#define STR 40

// ---------------------------------------------------------------------------
// Kernel 0: fp32 -> fp16 activation convert.  2x float4 per thread for MLP=2
// (front-batched LDG.128s) -> higher achieved HBM than the MLP=1 version.
// ---------------------------------------------------------------------------
__global__ void convert_x_kernel(const float* __restrict__ x) {
    int i = (blockIdx.x * blockDim.x + threadIdx.x) * 8;
    float4 v0 = *reinterpret_cast<const float4*>(x + i);
    float4 v1 = *reinterpret_cast<const float4*>(x + i + 4);
    __half2* o = reinterpret_cast<__half2*>(g_xh + i);
    o[0] = __floats2half2_rn(v0.x, v0.y);
    o[1] = __floats2half2_rn(v0.z, v0.w);
    o[2] = __floats2half2_rn(v1.x, v1.y);
    o[3] = __floats2half2_rn(v1.z, v1.w);
}

// ---------------------------------------------------------------------------
// Kernel 1: gemm1 (x @ Wgu) + fused SiLU-gate, in-loop dequant, pipelined.
// R7 byte-exact: BM=128 x BN=64 pairs, BK=32, double-buffered, ldmatrix,
// 256 threads (8 warps 2x4). Proven best configuration (1648.9 us).
// ---------------------------------------------------------------------------
__global__ void __launch_bounds__(256) gemm1_silu_kernel(
    const int*   __restrict__ gup,     // [E, H/2, 2I]
    const float* __restrict__ gus,     // [E, H/16, 2I]
    const float* __restrict__ pgs)     // scalar gscale
{
    __shared__ __half As[2][128 * STR];
    __shared__ __half Bg[2][64 * STR];
    __shared__ __half Bu[2][64 * STR];

    const int e   = blockIdx.z;
    const int bm0 = blockIdx.x * 128;   // m-tile fastest -> weight L2 reuse
    const int n0  = blockIdx.y * 64;
    const float gscale = __ldg(pgs);

    const int tid  = threadIdx.x;
    const int lane = tid & 31;
    const int wid  = tid >> 5;
    const int g    = lane >> 2;
    const int tg   = lane & 3;
    const int wm   = wid & 1;
    const int wn   = wid >> 1;

    float accg[4][2][4], accu[4][2][4];
#pragma unroll
    for (int a = 0; a < 4; a++)
#pragma unroll
        for (int b = 0; b < 2; b++)
#pragma unroll
            for (int c = 0; c < 4; c++) { accg[a][b][c] = 0.f; accu[a][b][c] = 0.f; }

    const __half* xg = g_xh + (size_t)(e * T_ + bm0) * H_;

    // ldmatrix lane addressing
    const int a_r = wm * 64 + (lane & 15);
    const int a_c = (lane >> 4) * 8;
    const int b_r = (lane & 7) + ((lane >> 4) << 3);
    const int b_c = ((lane >> 3) & 1) * 8;

    // B loader: col = tid&63, oct = (tid>>6)&1 (one 16-k scale block), gu = tid>>7
    const int bcol = tid & 63;
    const int boct = (tid >> 6) & 1;
    const int bgu  = tid >> 7;
    const int bncol = n0 + bcol + (bgu ? I_ : 0);

    int   pv[8];
    float bscale;

    auto loadB = [&](int k0) {
        const int kp0 = (k0 >> 1) + boct * 8;
        const int* p = gup + ((size_t)e * (H_ / 2) + kp0) * (2 * I_) + bncol;
#pragma unroll
        for (int j = 0; j < 8; j++) pv[j] = __ldg(p + (size_t)j * (2 * I_));
        bscale = __ldg(gus + ((size_t)e * (H_ / 16) + (kp0 >> 3)) * (2 * I_) + bncol) * gscale;
    };
    auto stsB = [&](int s) {
        uint32_t w[8];
#pragma unroll
        for (int j = 0; j < 8; j++)
            w[j] = pack2(fp4f(pv[j] & 15) * bscale, fp4f((pv[j] >> 4) & 15) * bscale);
        __half* d = (bgu ? Bu[s] : Bg[s]) + bcol * STR + 2 * (boct * 8);
        reinterpret_cast<uint4*>(d)[0] = make_uint4(w[0], w[1], w[2], w[3]);
        reinterpret_cast<uint4*>(d)[1] = make_uint4(w[4], w[5], w[6], w[7]);
    };
    auto loadA = [&](int s, int k0) {
#pragma unroll
        for (int i = 0; i < 2; i++) {
            const int u = tid + 256 * i;            // 0..511
            const int row = u >> 2, seg = (u & 3) * 8;
            cpasync16(As[s] + row * STR + seg, xg + (size_t)row * H_ + k0 + seg);
        }
    };

    // prologue
    loadB(0);
    loadA(0, 0);
    CP_COMMIT();
    stsB(0);
    CP_WAIT0();
    __syncthreads();

    const int NIT = H_ / 32;
    int s = 0;
    for (int it = 0; it < NIT; it++) {
        const bool more = (it + 1 < NIT);
        if (more) { loadB((it + 1) * 32); loadA(s ^ 1, (it + 1) * 32); }
        CP_COMMIT();

        // ---- compute: 2 k16 steps, ldmatrix fragments (R7-exact) ----
#pragma unroll
        for (int kk = 0; kk < 2; kk++) {
            uint32_t a[4][4];
#pragma unroll
            for (int mi = 0; mi < 4; mi++) {
                uint32_t p = (uint32_t)__cvta_generic_to_shared(
                    As[s] + (a_r + mi * 16) * STR + kk * 16 + a_c);
                LDSM4(a[mi][0], a[mi][1], a[mi][2], a[mi][3], p);
            }
            uint32_t bg[4], bu[4];
            {
                uint32_t pg = (uint32_t)__cvta_generic_to_shared(
                    Bg[s] + (wn * 16 + b_r) * STR + kk * 16 + b_c);
                LDSM4(bg[0], bg[1], bg[2], bg[3], pg);
                uint32_t pu = (uint32_t)__cvta_generic_to_shared(
                    Bu[s] + (wn * 16 + b_r) * STR + kk * 16 + b_c);
                LDSM4(bu[0], bu[1], bu[2], bu[3], pu);
            }
#pragma unroll
            for (int ni = 0; ni < 2; ni++) {
#pragma unroll
                for (int mi = 0; mi < 4; mi++) {
                    mma16816(accg[mi][ni][0], accg[mi][ni][1], accg[mi][ni][2], accg[mi][ni][3],
                             a[mi][0], a[mi][1], a[mi][2], a[mi][3],
                             bg[2 * ni], bg[2 * ni + 1]);
                    mma16816(accu[mi][ni][0], accu[mi][ni][1], accu[mi][ni][2], accu[mi][ni][3],
                             a[mi][0], a[mi][1], a[mi][2], a[mi][3],
                             bu[2 * ni], bu[2 * ni + 1]);
                }
            }
        }

        if (more) stsB(s ^ 1);
        CP_WAIT0();
        __syncthreads();
        s ^= 1;
    }

    // ---- epilogue: inter = up * silu(gate) ----
#pragma unroll
    for (int mi = 0; mi < 4; mi++) {
        const int r0 = bm0 + wm * 64 + mi * 16 + g;
#pragma unroll
        for (int ni = 0; ni < 2; ni++) {
            const int c0 = n0 + wn * 16 + ni * 8 + 2 * tg;
            const float i0 = accu[mi][ni][0] * silu_f(accg[mi][ni][0]);
            const float i1 = accu[mi][ni][1] * silu_f(accg[mi][ni][1]);
            const float i2 = accu[mi][ni][2] * silu_f(accg[mi][ni][2]);
            const float i3 = accu[mi][ni][3] * silu_f(accg[mi][ni][3]);
            *reinterpret_cast<__half2*>(g_inter + (size_t)(e * T_ + r0) * I_ + c0)
                = __floats2half2_rn(i0, i1);
            *reinterpret_cast<__half2*>(g_inter + (size_t)(e * T_ + r0 + 8) * I_ + c0)
                = __floats2half2_rn(i2, i3);
        }
    }
}

// ---------------------------------------------------------------------------
// Kernel 2: gemm2 (inter @ Wd) -> fp32, in-loop dequant, pipelined, ldmatrix.
// R7 byte-exact: BM=128 x BN=128, BK=32, double-buffered, warp tile 64x32.
// ---------------------------------------------------------------------------
__global__ void __launch_bounds__(256) gemm2_kernel(
    const int*   __restrict__ dpk,     // [E, I/2, H]
    const float* __restrict__ dsc,     // [E, I/16, H]
    const float* __restrict__ pgs,
    float*       __restrict__ out)     // [E*T, H]
{
    __shared__ __half As[2][128 * STR];
    __shared__ __half Bs[2][128 * STR];

    const int e   = blockIdx.z;
    const int bm0 = blockIdx.x * 128;
    const int n0  = blockIdx.y * 128;
    const float gscale = __ldg(pgs);

    const int tid  = threadIdx.x;
    const int lane = tid & 31;
    const int wid  = tid >> 5;
    const int g    = lane >> 2;
    const int tg   = lane & 3;
    const int wm   = wid & 1;
    const int wn   = wid >> 1;

    float acc[4][4][4];
#pragma unroll
    for (int a = 0; a < 4; a++)
#pragma unroll
        for (int b = 0; b < 4; b++)
#pragma unroll
            for (int c = 0; c < 4; c++) acc[a][b][c] = 0.f;

    const __half* ag = g_inter + (size_t)(e * T_ + bm0) * I_;

    const int a_r = wm * 64 + (lane & 15);
    const int a_c = (lane >> 4) * 8;
    const int b_r = (lane & 7) + ((lane >> 4) << 3);
    const int b_c = ((lane >> 3) & 1) * 8;

    const int bcol = tid & 127;
    const int boct = tid >> 7;

    int   pv[8];
    float bscale;

    auto loadB = [&](int k0) {
        const int kp0 = (k0 >> 1) + boct * 8;
        const int* p = dpk + ((size_t)e * (I_ / 2) + kp0) * H_ + n0 + bcol;
#pragma unroll
        for (int j = 0; j < 8; j++) pv[j] = __ldg(p + (size_t)j * H_);
        bscale = __ldg(dsc + ((size_t)e * (I_ / 16) + (kp0 >> 3)) * H_ + n0 + bcol) * gscale;
    };
    auto stsB = [&](int s) {
        uint32_t w[8];
#pragma unroll
        for (int j = 0; j < 8; j++)
            w[j] = pack2(fp4f(pv[j] & 15) * bscale, fp4f((pv[j] >> 4) & 15) * bscale);
        __half* d = Bs[s] + bcol * STR + 2 * (boct * 8);
        reinterpret_cast<uint4*>(d)[0] = make_uint4(w[0], w[1], w[2], w[3]);
        reinterpret_cast<uint4*>(d)[1] = make_uint4(w[4], w[5], w[6], w[7]);
    };
    auto loadA = [&](int s, int k0) {
#pragma unroll
        for (int i = 0; i < 2; i++) {
            const int u = tid + 256 * i;
            const int row = u >> 2, seg = (u & 3) * 8;
            cpasync16(As[s] + row * STR + seg, ag + (size_t)row * I_ + k0 + seg);
        }
    };

    loadB(0);
    loadA(0, 0);
    CP_COMMIT();
    stsB(0);
    CP_WAIT0();
    __syncthreads();

    const int NIT = I_ / 32;
    int s = 0;
    for (int it = 0; it < NIT; it++) {
        const bool more = (it + 1 < NIT);
        if (more) { loadB((it + 1) * 32); loadA(s ^ 1, (it + 1) * 32); }
        CP_COMMIT();

#pragma unroll
        for (int kk = 0; kk < 2; kk++) {
            uint32_t a[4][4];
#pragma unroll
            for (int mi = 0; mi < 4; mi++) {
                uint32_t p = (uint32_t)__cvta_generic_to_shared(
                    As[s] + (a_r + mi * 16) * STR + kk * 16 + a_c);
                LDSM4(a[mi][0], a[mi][1], a[mi][2], a[mi][3], p);
            }
            uint32_t bq[2][4];
#pragma unroll
            for (int h = 0; h < 2; h++) {
                uint32_t p = (uint32_t)__cvta_generic_to_shared(
                    Bs[s] + (wn * 32 + h * 16 + b_r) * STR + kk * 16 + b_c);
                LDSM4(bq[h][0], bq[h][1], bq[h][2], bq[h][3], p);
            }
#pragma unroll
            for (int ni = 0; ni < 4; ni++) {
                const uint32_t b0 = bq[ni >> 1][2 * (ni & 1)];
                const uint32_t b1 = bq[ni >> 1][2 * (ni & 1) + 1];
#pragma unroll
                for (int mi = 0; mi < 4; mi++) {
                    mma16816(acc[mi][ni][0], acc[mi][ni][1], acc[mi][ni][2], acc[mi][ni][3],
                             a[mi][0], a[mi][1], a[mi][2], a[mi][3], b0, b1);
                }
            }
        }

        if (more) stsB(s ^ 1);
        CP_WAIT0();
        __syncthreads();
        s ^= 1;
    }

    // ---- epilogue ----
#pragma unroll
    for (int mi = 0; mi < 4; mi++) {
        const int r0 = bm0 + wm * 64 + mi * 16 + g;
#pragma unroll
        for (int ni = 0; ni < 4; ni++) {
            const int c0 = n0 + wn * 32 + ni * 8 + 2 * tg;
            *reinterpret_cast<float2*>(out + (size_t)(e * T_ + r0) * H_ + c0)
                = make_float2(acc[mi][ni][0], acc[mi][ni][1]);
            *reinterpret_cast<float2*>(out + (size_t)(e * T_ + r0 + 8) * H_ + c0)
                = make_float2(acc[mi][ni][2], acc[mi][ni][3]);
        }
    }
}

// ---------------------------------------------------------------------------
// Launch
// ---------------------------------------------------------------------------
extern "C" void kernel_launch(void* const* d_in, const int* in_sizes, int n_in,
                              void* d_out, int out_size) {
    const float* x   = (const float*)d_in[0];
    const int*   gup = (const int*)  d_in[1];
    const float* gus = (const float*)d_in[2];
    const float* gug = (const float*)d_in[3];
    const int*   dpk = (const int*)  d_in[4];
    const float* dsc = (const float*)d_in[5];
    const float* dgs = (const float*)d_in[6];
    float* out = (float*)d_out;

    convert_x_kernel<<<(E_ * T_ * H_) / 2048, 256>>>(x);

    gemm1_silu_kernel<<<dim3(T_ / 128, I_ / 64, E_), 256>>>(gup, gus, gug);
    gemm2_kernel<<<dim3(T_ / 128, H_ / 128, E_), 256>>>(dpk, dsc, dgs, out);
}